// round 2
// baseline (speedup 1.0000x reference)
#include <cuda_runtime.h>
#include <math.h>

// OmegaRule: B=8, L=8192, D=256, W=64 -> NW=128 windows, T=B*W=512 rows/window.
#define BB 8
#define LL 8192
#define DD 256
#define WW 64
#define NW 128
#define TT 512

// Scratch (device globals; no allocation allowed). 3 x 32MB.
__device__ float g_Skk[NW * DD * DD];
__device__ float g_Svk[NW * DD * DD];
__device__ float g_Ms [NW * DD * DD];

// ---------------------------------------------------------------------------
// K1: per-window moment matrices.
//   Skk[n][x][y] = sum_t g_t * k[t][x] * k[t][y]
//   Svk[n][x][y] = sum_t g_t * v[t][x] * k[t][y]
// One CTA computes a 64x64 tile of BOTH (they share the k "B" operand).
// grid = (16 tiles, NW), block = 256, 4x4 register microtiles, K-chunk = 16.
// ---------------------------------------------------------------------------
__global__ __launch_bounds__(256) void k1_moments(
    const float* __restrict__ keys,
    const float* __restrict__ values,
    const float* __restrict__ gammas)
{
    __shared__ float4 sGK[16][16];  // [t in chunk][x float4]  (gamma * k, x-block)
    __shared__ float4 sGV[16][16];  // (gamma * v, x-block)
    __shared__ float4 sK [16][16];  // (k, y-block)

    const int n   = blockIdx.y;
    const int ib  = blockIdx.x >> 2;   // x block (0..3)
    const int jb  = blockIdx.x & 3;    // y block (0..3)
    const int tid = threadIdx.x;
    const int tr  = tid >> 4;          // 0..15 : t within chunk (load role)
    const int tc  = tid & 15;          // 0..15 : float4 column  (load role)
    const int tx  = tid & 15;          // compute: y micro-col
    const int ty  = tid >> 4;          // compute: x micro-row

    float acc1[4][4], acc2[4][4];
    #pragma unroll
    for (int r = 0; r < 4; ++r)
        #pragma unroll
        for (int c = 0; c < 4; ++c) { acc1[r][c] = 0.f; acc2[r][c] = 0.f; }

    for (int ch = 0; ch < TT / 16; ++ch) {
        const int t = ch * 16 + tr;           // 0..511
        const int b = t >> 6;
        const int w = t & 63;
        const long row = ((long)b * LL + (long)n * WW + w) * DD;
        const float g = __ldg(&gammas[(long)b * LL + (long)n * WW + w]);
        float4 kx = *(const float4*)(keys   + row + ib * 64 + tc * 4);
        float4 vx = *(const float4*)(values + row + ib * 64 + tc * 4);
        float4 ky = *(const float4*)(keys   + row + jb * 64 + tc * 4);
        sGK[tr][tc] = make_float4(g * kx.x, g * kx.y, g * kx.z, g * kx.w);
        sGV[tr][tc] = make_float4(g * vx.x, g * vx.y, g * vx.z, g * vx.w);
        sK [tr][tc] = ky;
        __syncthreads();

        #pragma unroll
        for (int tk = 0; tk < 16; ++tk) {
            float4 a1 = sGK[tk][ty];
            float4 a2 = sGV[tk][ty];
            float4 bb = sK [tk][tx];
            float av1[4] = {a1.x, a1.y, a1.z, a1.w};
            float av2[4] = {a2.x, a2.y, a2.z, a2.w};
            float bv [4] = {bb.x, bb.y, bb.z, bb.w};
            #pragma unroll
            for (int r = 0; r < 4; ++r)
                #pragma unroll
                for (int c = 0; c < 4; ++c) {
                    acc1[r][c] += av1[r] * bv[c];
                    acc2[r][c] += av2[r] * bv[c];
                }
        }
        __syncthreads();
    }

    float* skk = g_Skk + (long)n * DD * DD;
    float* svk = g_Svk + (long)n * DD * DD;
    #pragma unroll
    for (int r = 0; r < 4; ++r) {
        const int x  = ib * 64 + ty * 4 + r;
        const int y0 = jb * 64 + tx * 4;
        *(float4*)(skk + (long)x * DD + y0) =
            make_float4(acc1[r][0], acc1[r][1], acc1[r][2], acc1[r][3]);
        *(float4*)(svk + (long)x * DD + y0) =
            make_float4(acc2[r][0], acc2[r][1], acc2[r][2], acc2[r][3]);
    }
}

// ---------------------------------------------------------------------------
// K2: sequential window scan; rows of M are independent:
//   row_o <- a*row_o - row_o @ Skk_n + Svk_n[o,:]
// grid = 64 CTAs x 4 rows, block = 256 (thread j owns output column j).
// Skk column loads are double-buffered in 16-deep blocks to cover L2 latency.
// ---------------------------------------------------------------------------
__global__ __launch_bounds__(256) void k2_scan(const float* __restrict__ alpha_p)
{
    __shared__ float srow[4][DD];
    const int j  = threadIdx.x;
    const int o0 = blockIdx.x * 4;
    const float a = 1.f / (1.f + expf(-alpha_p[0]));

    #pragma unroll
    for (int r = 0; r < 4; ++r) srow[r][j] = 0.f;
    __syncthreads();

    for (int n = 0; n < NW; ++n) {
        const float* skk = g_Skk + (long)n * DD * DD;
        const float* svk = g_Svk + (long)n * DD * DD;
        float acc0 = 0.f, acc1 = 0.f, acc2 = 0.f, acc3 = 0.f;

        float sb[16];
        #pragma unroll
        for (int u = 0; u < 16; ++u) sb[u] = skk[(long)u * DD + j];

        for (int blk = 0; blk < 16; ++blk) {
            float sn[16];
            if (blk < 15) {
                const float* p = skk + (long)(blk + 1) * 16 * DD + j;
                #pragma unroll
                for (int u = 0; u < 16; ++u) sn[u] = p[(long)u * DD];
            } else {
                #pragma unroll
                for (int u = 0; u < 16; ++u) sn[u] = 0.f;
            }
            const int dbase = blk * 16;
            #pragma unroll
            for (int q = 0; q < 4; ++q) {
                float4 m0 = *(const float4*)&srow[0][dbase + q * 4];
                float4 m1 = *(const float4*)&srow[1][dbase + q * 4];
                float4 m2 = *(const float4*)&srow[2][dbase + q * 4];
                float4 m3 = *(const float4*)&srow[3][dbase + q * 4];
                float s0 = sb[q * 4 + 0], s1 = sb[q * 4 + 1];
                float s2 = sb[q * 4 + 2], s3 = sb[q * 4 + 3];
                acc0 += m0.x * s0 + m0.y * s1 + m0.z * s2 + m0.w * s3;
                acc1 += m1.x * s0 + m1.y * s1 + m1.z * s2 + m1.w * s3;
                acc2 += m2.x * s0 + m2.y * s1 + m2.z * s2 + m2.w * s3;
                acc3 += m3.x * s0 + m3.y * s1 + m3.z * s2 + m3.w * s3;
            }
            #pragma unroll
            for (int u = 0; u < 16; ++u) sb[u] = sn[u];
        }

        const float nv0 = a * srow[0][j] - acc0 + svk[(long)(o0 + 0) * DD + j];
        const float nv1 = a * srow[1][j] - acc1 + svk[(long)(o0 + 1) * DD + j];
        const float nv2 = a * srow[2][j] - acc2 + svk[(long)(o0 + 2) * DD + j];
        const float nv3 = a * srow[3][j] - acc3 + svk[(long)(o0 + 3) * DD + j];
        __syncthreads();   // everyone done READING srow for this step
        srow[0][j] = nv0; srow[1][j] = nv1; srow[2][j] = nv2; srow[3][j] = nv3;
        float* ms = g_Ms + (long)n * DD * DD;
        ms[(long)(o0 + 0) * DD + j] = nv0;
        ms[(long)(o0 + 1) * DD + j] = nv1;
        ms[(long)(o0 + 2) * DD + j] = nv2;
        ms[(long)(o0 + 3) * DD + j] = nv3;
        __syncthreads();   // new srow visible before next step
    }
}

// ---------------------------------------------------------------------------
// K3: retrieval. out[t][o] = sum_d q[t][d] * Ms[n][o][d]   (t = b*64+w, 512 rows)
// grid = (32 tiles, NW): 8 t-blocks x 4 o-blocks of 64x64. block = 256.
// Reduction over d => transposed smem staging with +1 padding.
// ---------------------------------------------------------------------------
__global__ __launch_bounds__(256) void k3_out(
    const float* __restrict__ queries, float* __restrict__ out)
{
    __shared__ float sQ[16][65];   // [d in chunk][t]
    __shared__ float sM[16][65];   // [d in chunk][o]

    const int n   = blockIdx.y;
    const int tb  = blockIdx.x >> 2;  // t block 0..7
    const int ob  = blockIdx.x & 3;   // o block 0..3
    const int tid = threadIdx.x;
    const int lr  = tid >> 2;         // 0..63 tile row (load role)
    const int lc  = tid & 3;          // float4 chunk   (load role)
    const int tx  = tid & 15;         // compute: o micro
    const int ty  = tid >> 4;         // compute: t micro

    const float* Ms = g_Ms + (long)n * DD * DD;

    float acc[4][4];
    #pragma unroll
    for (int r = 0; r < 4; ++r)
        #pragma unroll
        for (int c = 0; c < 4; ++c) acc[r][c] = 0.f;

    // global row address for this thread's load row of q
    const int t_ld = tb * 64 + lr;
    const int b_ld = t_ld >> 6;
    const int w_ld = t_ld & 63;
    const long qrow = ((long)b_ld * LL + (long)n * WW + w_ld) * DD;
    const long mrow = (long)(ob * 64 + lr) * DD;

    for (int ch = 0; ch < 16; ++ch) {
        float4 qv = *(const float4*)(queries + qrow + ch * 16 + lc * 4);
        float4 mv = *(const float4*)(Ms + mrow + ch * 16 + lc * 4);
        sQ[lc * 4 + 0][lr] = qv.x; sQ[lc * 4 + 1][lr] = qv.y;
        sQ[lc * 4 + 2][lr] = qv.z; sQ[lc * 4 + 3][lr] = qv.w;
        sM[lc * 4 + 0][lr] = mv.x; sM[lc * 4 + 1][lr] = mv.y;
        sM[lc * 4 + 2][lr] = mv.z; sM[lc * 4 + 3][lr] = mv.w;
        __syncthreads();

        #pragma unroll
        for (int dk = 0; dk < 16; ++dk) {
            float av[4], bv[4];
            #pragma unroll
            for (int r = 0; r < 4; ++r) av[r] = sQ[dk][ty * 4 + r];
            #pragma unroll
            for (int c = 0; c < 4; ++c) bv[c] = sM[dk][tx * 4 + c];
            #pragma unroll
            for (int r = 0; r < 4; ++r)
                #pragma unroll
                for (int c = 0; c < 4; ++c) acc[r][c] += av[r] * bv[c];
        }
        __syncthreads();
    }

    #pragma unroll
    for (int r = 0; r < 4; ++r) {
        const int t = tb * 64 + ty * 4 + r;
        const int b = t >> 6;
        const int w = t & 63;
        const long addr = ((long)b * LL + (long)n * WW + w) * DD + ob * 64 + tx * 4;
        *(float4*)(out + addr) = make_float4(acc[r][0], acc[r][1], acc[r][2], acc[r][3]);
    }
}

// ---------------------------------------------------------------------------
extern "C" void kernel_launch(void* const* d_in, const int* in_sizes, int n_in,
                              void* d_out, int out_size)
{
    const float* keys    = (const float*)d_in[0];
    const float* values  = (const float*)d_in[1];
    const float* queries = (const float*)d_in[2];
    const float* gammas  = (const float*)d_in[3];
    const float* alpha   = (const float*)d_in[4];
    float* out = (float*)d_out;

    k1_moments<<<dim3(16, NW), 256>>>(keys, values, gammas);
    k2_scan<<<64, 256>>>(alpha);
    k3_out<<<dim3(32, NW), 256>>>(queries, out);
}

// round 3
// speedup vs baseline: 1.6075x; 1.6075x over previous
#include <cuda_runtime.h>
#include <math.h>

// OmegaRule: B=8, L=8192, D=256, W=64 -> NW=128 windows, T=B*W=512 rows/window.
#define BB 8
#define LL 8192
#define DD 256
#define WW 64
#define NW 128
#define TT 512
#define CH 8     // chunks
#define CS 16    // windows per chunk (CH*CS == NW)
#define MATSZ (DD * DD)

// Scratch (device globals; no allocation allowed).
__device__ float g_Skk[NW * MATSZ];
__device__ float g_Svk[NW * MATSZ];
__device__ float g_Ms [NW * MATSZ];   // phase A: local scans; phase C: fixed up in place
__device__ float g_P  [NW * MATSZ];   // phase A: within-chunk prefix products of A = aI - Skk
__device__ float g_E  [CH * MATSZ];   // phase B: chunk-end global states

// ---- packed fp32x2 helpers (Blackwell FFMA2 — PTX-only path) --------------
typedef unsigned long long u64;
__device__ __forceinline__ void ffma2(u64& acc, u64 a, u64 b) {
    asm("fma.rn.f32x2 %0, %1, %2, %0;" : "+l"(acc) : "l"(a), "l"(b));
}
__device__ __forceinline__ u64 pack2f(float x, float y) {
    u64 r; asm("mov.b64 %0, {%1, %2};" : "=l"(r) : "f"(x), "f"(y)); return r;
}
__device__ __forceinline__ float hsum2(u64 v) {
    float x, y; asm("mov.b64 {%0, %1}, %2;" : "=f"(x), "=f"(y) : "l"(v));
    return x + y;
}

// ---------------------------------------------------------------------------
// K1: per-window moment matrices (unchanged from passing version).
// ---------------------------------------------------------------------------
__global__ __launch_bounds__(256) void k1_moments(
    const float* __restrict__ keys,
    const float* __restrict__ values,
    const float* __restrict__ gammas)
{
    __shared__ float4 sGK[16][16];
    __shared__ float4 sGV[16][16];
    __shared__ float4 sK [16][16];

    const int n   = blockIdx.y;
    const int ib  = blockIdx.x >> 2;
    const int jb  = blockIdx.x & 3;
    const int tid = threadIdx.x;
    const int tr  = tid >> 4;
    const int tc  = tid & 15;
    const int tx  = tid & 15;
    const int ty  = tid >> 4;

    float acc1[4][4], acc2[4][4];
    #pragma unroll
    for (int r = 0; r < 4; ++r)
        #pragma unroll
        for (int c = 0; c < 4; ++c) { acc1[r][c] = 0.f; acc2[r][c] = 0.f; }

    for (int ch = 0; ch < TT / 16; ++ch) {
        const int t = ch * 16 + tr;
        const int b = t >> 6;
        const int w = t & 63;
        const long row = ((long)b * LL + (long)n * WW + w) * DD;
        const float g = __ldg(&gammas[(long)b * LL + (long)n * WW + w]);
        float4 kx = *(const float4*)(keys   + row + ib * 64 + tc * 4);
        float4 vx = *(const float4*)(values + row + ib * 64 + tc * 4);
        float4 ky = *(const float4*)(keys   + row + jb * 64 + tc * 4);
        sGK[tr][tc] = make_float4(g * kx.x, g * kx.y, g * kx.z, g * kx.w);
        sGV[tr][tc] = make_float4(g * vx.x, g * vx.y, g * vx.z, g * vx.w);
        sK [tr][tc] = ky;
        __syncthreads();

        #pragma unroll
        for (int tk = 0; tk < 16; ++tk) {
            float4 a1 = sGK[tk][ty];
            float4 a2 = sGV[tk][ty];
            float4 bb = sK [tk][tx];
            float av1[4] = {a1.x, a1.y, a1.z, a1.w};
            float av2[4] = {a2.x, a2.y, a2.z, a2.w};
            float bv [4] = {bb.x, bb.y, bb.z, bb.w};
            #pragma unroll
            for (int r = 0; r < 4; ++r)
                #pragma unroll
                for (int c = 0; c < 4; ++c) {
                    acc1[r][c] += av1[r] * bv[c];
                    acc2[r][c] += av2[r] * bv[c];
                }
        }
        __syncthreads();
    }

    float* skk = g_Skk + (long)n * MATSZ;
    float* svk = g_Svk + (long)n * MATSZ;
    #pragma unroll
    for (int r = 0; r < 4; ++r) {
        const int x  = ib * 64 + ty * 4 + r;
        const int y0 = jb * 64 + tx * 4;
        *(float4*)(skk + (long)x * DD + y0) =
            make_float4(acc1[r][0], acc1[r][1], acc1[r][2], acc1[r][3]);
        *(float4*)(svk + (long)x * DD + y0) =
            make_float4(acc2[r][0], acc2[r][1], acc2[r][2], acc2[r][3]);
    }
}

// ---------------------------------------------------------------------------
// Phase A: per-chunk local scan + prefix products.
//   M rows:  m <- a*m - m@Skk + svk_row   (zero init)
//   P rows:  p <- a*p - p@Skk             (identity init)  [skipped for chunk 0]
// grid = (64 row-groups, CH chunks), block = 256. Thread j owns column j.
// ---------------------------------------------------------------------------
__global__ __launch_bounds__(256) void kA_local(const float* __restrict__ alpha_p)
{
    __shared__ float srow[8][DD];   // rows 0-3: M, rows 4-7: P
    const int j  = threadIdx.x;
    const int c  = blockIdx.y;
    const int o0 = blockIdx.x * 4;
    const float a = 1.f / (1.f + expf(-alpha_p[0]));
    const bool doP = (c > 0);

    #pragma unroll
    for (int r = 0; r < 4; ++r) {
        srow[r][j] = 0.f;
        srow[4 + r][j] = (j == o0 + r) ? 1.f : 0.f;
    }
    __syncthreads();

    for (int s = 0; s < CS; ++s) {
        const int n = c * CS + s;
        const float* skk = g_Skk + (long)n * MATSZ;
        const float* svk = g_Svk + (long)n * MATSZ;

        // issue svk loads early (consumed at window end)
        const float sv0 = svk[(long)(o0 + 0) * DD + j];
        const float sv1 = svk[(long)(o0 + 1) * DD + j];
        const float sv2 = svk[(long)(o0 + 2) * DD + j];
        const float sv3 = svk[(long)(o0 + 3) * DD + j];

        u64 accM[4] = {0, 0, 0, 0};
        u64 accP[4] = {0, 0, 0, 0};

        float sb[16];
        #pragma unroll
        for (int u = 0; u < 16; ++u) sb[u] = skk[(long)u * DD + j];

        #pragma unroll
        for (int blk = 0; blk < 16; ++blk) {
            float sn[16];
            if (blk < 15) {
                const float* p = skk + (long)(blk + 1) * 16 * DD + j;
                #pragma unroll
                for (int u = 0; u < 16; ++u) sn[u] = p[(long)u * DD];
            } else {
                #pragma unroll
                for (int u = 0; u < 16; ++u) sn[u] = 0.f;
            }
            u64 sp[8];
            #pragma unroll
            for (int p = 0; p < 8; ++p) sp[p] = pack2f(sb[2 * p], sb[2 * p + 1]);

            const int db = blk * 16;
            #pragma unroll
            for (int r = 0; r < 4; ++r) {
                const u64* mrow = (const u64*)&srow[r][db];
                #pragma unroll
                for (int p = 0; p < 8; ++p) ffma2(accM[r], mrow[p], sp[p]);
            }
            if (doP) {
                #pragma unroll
                for (int r = 0; r < 4; ++r) {
                    const u64* prow = (const u64*)&srow[4 + r][db];
                    #pragma unroll
                    for (int p = 0; p < 8; ++p) ffma2(accP[r], prow[p], sp[p]);
                }
            }
            #pragma unroll
            for (int u = 0; u < 16; ++u) sb[u] = sn[u];
        }

        float nM[4], nP[4];
        const float svv[4] = {sv0, sv1, sv2, sv3};
        #pragma unroll
        for (int r = 0; r < 4; ++r) {
            nM[r] = a * srow[r][j] - hsum2(accM[r]) + svv[r];
            nP[r] = doP ? (a * srow[4 + r][j] - hsum2(accP[r])) : 0.f;
        }
        __syncthreads();
        float* ms = g_Ms + (long)n * MATSZ;
        #pragma unroll
        for (int r = 0; r < 4; ++r) {
            srow[r][j] = nM[r];
            ms[(long)(o0 + r) * DD + j] = nM[r];
        }
        if (doP) {
            float* pp = g_P + (long)n * MATSZ;
            #pragma unroll
            for (int r = 0; r < 4; ++r) {
                srow[4 + r][j] = nP[r];
                pp[(long)(o0 + r) * DD + j] = nP[r];
            }
        }
        __syncthreads();
    }
}

// ---------------------------------------------------------------------------
// Phase B: sequential combine over chunk ends (7 steps).
//   E_0 = Mloc_end(chunk 0);  E_c = E_{c-1} @ P_end(c) + Mloc_end(c)
// grid = 64, block = 256.
// ---------------------------------------------------------------------------
__global__ __launch_bounds__(256) void kB_combine()
{
    __shared__ float srow[4][DD];
    const int j  = threadIdx.x;
    const int o0 = blockIdx.x * 4;

    // E_0
    {
        const float* m0 = g_Ms + (long)(CS - 1) * MATSZ;
        #pragma unroll
        for (int r = 0; r < 4; ++r) {
            const float v = m0[(long)(o0 + r) * DD + j];
            srow[r][j] = v;
            g_E[(long)(o0 + r) * DD + j] = v;
        }
    }
    __syncthreads();

    for (int c = 1; c < CH; ++c) {
        const long base = (long)(c * CS + CS - 1) * MATSZ;
        const float* pm = g_P  + base;
        const float* mm = g_Ms + base;

        const float me0 = mm[(long)(o0 + 0) * DD + j];
        const float me1 = mm[(long)(o0 + 1) * DD + j];
        const float me2 = mm[(long)(o0 + 2) * DD + j];
        const float me3 = mm[(long)(o0 + 3) * DD + j];

        u64 acc[4] = {0, 0, 0, 0};
        float sb[16];
        #pragma unroll
        for (int u = 0; u < 16; ++u) sb[u] = pm[(long)u * DD + j];

        #pragma unroll
        for (int blk = 0; blk < 16; ++blk) {
            float sn[16];
            if (blk < 15) {
                const float* p = pm + (long)(blk + 1) * 16 * DD + j;
                #pragma unroll
                for (int u = 0; u < 16; ++u) sn[u] = p[(long)u * DD];
            } else {
                #pragma unroll
                for (int u = 0; u < 16; ++u) sn[u] = 0.f;
            }
            u64 sp[8];
            #pragma unroll
            for (int p = 0; p < 8; ++p) sp[p] = pack2f(sb[2 * p], sb[2 * p + 1]);
            const int db = blk * 16;
            #pragma unroll
            for (int r = 0; r < 4; ++r) {
                const u64* erow = (const u64*)&srow[r][db];
                #pragma unroll
                for (int p = 0; p < 8; ++p) ffma2(acc[r], erow[p], sp[p]);
            }
            #pragma unroll
            for (int u = 0; u < 16; ++u) sb[u] = sn[u];
        }

        const float mev[4] = {me0, me1, me2, me3};
        float nE[4];
        #pragma unroll
        for (int r = 0; r < 4; ++r) nE[r] = hsum2(acc[r]) + mev[r];
        __syncthreads();
        float* e = g_E + (long)c * MATSZ;
        #pragma unroll
        for (int r = 0; r < 4; ++r) {
            srow[r][j] = nE[r];
            e[(long)(o0 + r) * DD + j] = nE[r];
        }
        __syncthreads();
    }
}

// ---------------------------------------------------------------------------
// Phase C: fix-up GEMMs (parallel): Ms[n] += E_{c-1} @ P_n  for n in chunks 1..7.
// grid = (16 tiles, NW - CS), block = 256. 64x64 tiles, 4x4 micro.
// ---------------------------------------------------------------------------
__global__ __launch_bounds__(256) void kC_fix()
{
    __shared__ float sE[16][65];   // [d][x]  (E staged transposed)
    __shared__ float sP[16][65];   // [d][y]

    const int nw  = blockIdx.y + CS;       // window 16..127
    const int c   = nw >> 4;               // chunk 1..7
    const int ib  = blockIdx.x >> 2;       // x block
    const int jb  = blockIdx.x & 3;        // y block
    const int tid = threadIdx.x;
    const int lr  = tid >> 2;              // 0..63
    const int lc  = tid & 3;               // float4 chunk
    const int pr  = tid >> 4;              // 0..15 (P load row)
    const int pc  = tid & 15;              // 0..15 (P load float4 col)
    const int tx  = tid & 15;
    const int ty  = tid >> 4;

    const float* E = g_E + (long)(c - 1) * MATSZ;
    const float* P = g_P + (long)nw * MATSZ;
    float*      Ms = g_Ms + (long)nw * MATSZ;

    float acc[4][4];
    #pragma unroll
    for (int r = 0; r < 4; ++r)
        #pragma unroll
        for (int q = 0; q < 4; ++q) acc[r][q] = 0.f;

    const long erow = (long)(ib * 64 + lr) * DD;

    for (int ch = 0; ch < 16; ++ch) {
        float4 ev = *(const float4*)(E + erow + ch * 16 + lc * 4);
        float4 pv = *(const float4*)(P + (long)(ch * 16 + pr) * DD + jb * 64 + pc * 4);
        sE[lc * 4 + 0][lr] = ev.x; sE[lc * 4 + 1][lr] = ev.y;
        sE[lc * 4 + 2][lr] = ev.z; sE[lc * 4 + 3][lr] = ev.w;
        sP[pr][pc * 4 + 0] = pv.x; sP[pr][pc * 4 + 1] = pv.y;
        sP[pr][pc * 4 + 2] = pv.z; sP[pr][pc * 4 + 3] = pv.w;
        __syncthreads();

        #pragma unroll
        for (int dk = 0; dk < 16; ++dk) {
            float av[4], bv[4];
            #pragma unroll
            for (int r = 0; r < 4; ++r) av[r] = sE[dk][ty * 4 + r];
            #pragma unroll
            for (int q = 0; q < 4; ++q) bv[q] = sP[dk][tx * 4 + q];
            #pragma unroll
            for (int r = 0; r < 4; ++r)
                #pragma unroll
                for (int q = 0; q < 4; ++q) acc[r][q] += av[r] * bv[q];
        }
        __syncthreads();
    }

    #pragma unroll
    for (int r = 0; r < 4; ++r) {
        float* dst = Ms + (long)(ib * 64 + ty * 4 + r) * DD + jb * 64 + tx * 4;
        float4 old = *(const float4*)dst;
        *(float4*)dst = make_float4(old.x + acc[r][0], old.y + acc[r][1],
                                    old.z + acc[r][2], old.w + acc[r][3]);
    }
}

// ---------------------------------------------------------------------------
// K3: retrieval (unchanged). out[t][o] = sum_d q[t][d] * Ms[n][o][d]
// ---------------------------------------------------------------------------
__global__ __launch_bounds__(256) void k3_out(
    const float* __restrict__ queries, float* __restrict__ out)
{
    __shared__ float sQ[16][65];
    __shared__ float sM[16][65];

    const int n   = blockIdx.y;
    const int tb  = blockIdx.x >> 2;
    const int ob  = blockIdx.x & 3;
    const int tid = threadIdx.x;
    const int lr  = tid >> 2;
    const int lc  = tid & 3;
    const int tx  = tid & 15;
    const int ty  = tid >> 4;

    const float* Ms = g_Ms + (long)n * MATSZ;

    float acc[4][4];
    #pragma unroll
    for (int r = 0; r < 4; ++r)
        #pragma unroll
        for (int c = 0; c < 4; ++c) acc[r][c] = 0.f;

    const int t_ld = tb * 64 + lr;
    const int b_ld = t_ld >> 6;
    const int w_ld = t_ld & 63;
    const long qrow = ((long)b_ld * LL + (long)n * WW + w_ld) * DD;
    const long mrow = (long)(ob * 64 + lr) * DD;

    for (int ch = 0; ch < 16; ++ch) {
        float4 qv = *(const float4*)(queries + qrow + ch * 16 + lc * 4);
        float4 mv = *(const float4*)(Ms + mrow + ch * 16 + lc * 4);
        sQ[lc * 4 + 0][lr] = qv.x; sQ[lc * 4 + 1][lr] = qv.y;
        sQ[lc * 4 + 2][lr] = qv.z; sQ[lc * 4 + 3][lr] = qv.w;
        sM[lc * 4 + 0][lr] = mv.x; sM[lc * 4 + 1][lr] = mv.y;
        sM[lc * 4 + 2][lr] = mv.z; sM[lc * 4 + 3][lr] = mv.w;
        __syncthreads();

        #pragma unroll
        for (int dk = 0; dk < 16; ++dk) {
            float av[4], bv[4];
            #pragma unroll
            for (int r = 0; r < 4; ++r) av[r] = sQ[dk][ty * 4 + r];
            #pragma unroll
            for (int c = 0; c < 4; ++c) bv[c] = sM[dk][tx * 4 + c];
            #pragma unroll
            for (int r = 0; r < 4; ++r)
                #pragma unroll
                for (int c = 0; c < 4; ++c) acc[r][c] += av[r] * bv[c];
        }
        __syncthreads();
    }

    #pragma unroll
    for (int r = 0; r < 4; ++r) {
        const int t = tb * 64 + ty * 4 + r;
        const int b = t >> 6;
        const int w = t & 63;
        const long addr = ((long)b * LL + (long)n * WW + w) * DD + ob * 64 + tx * 4;
        *(float4*)(out + addr) = make_float4(acc[r][0], acc[r][1], acc[r][2], acc[r][3]);
    }
}

// ---------------------------------------------------------------------------
extern "C" void kernel_launch(void* const* d_in, const int* in_sizes, int n_in,
                              void* d_out, int out_size)
{
    const float* keys    = (const float*)d_in[0];
    const float* values  = (const float*)d_in[1];
    const float* queries = (const float*)d_in[2];
    const float* gammas  = (const float*)d_in[3];
    const float* alpha   = (const float*)d_in[4];
    float* out = (float*)d_out;

    k1_moments<<<dim3(16, NW), 256>>>(keys, values, gammas);
    kA_local<<<dim3(64, CH), 256>>>(alpha);
    kB_combine<<<64, 256>>>();
    kC_fix<<<dim3(16, NW - CS), 256>>>();
    k3_out<<<dim3(32, NW), 256>>>(queries, out);
}